// round 11
// baseline (speedup 1.0000x reference)
#include <cuda_runtime.h>
#include <cstdint>

#define NNODE 50000
#define NEDGE 800000
#define EPS_LN 1e-5f
#define EDGE_TTILES 50000   // 800000/16
#define NODE_TTILES 3125    // 50000/16
#define NTHREADS 512
#define NTEAMS 4

__device__ __align__(16) float g_Pa[NNODE*128];
__device__ __align__(16) float g_Pb[NNODE*128];
__device__ __align__(16) float g_Pn[NNODE*128];
__device__ __align__(16) float g_agg[NNODE*128];

__device__ __forceinline__ uint32_t f2tf(float f){
    uint32_t u; asm("cvt.rna.tf32.f32 %0, %1;" : "=r"(u) : "f"(f)); return u;
}
__device__ __forceinline__ float sigl(float v){ return v * (1.0f/(1.0f + __expf(-v))); }

#define TBAR(id) asm volatile("bar.sync %0, 128;" :: "r"(id) : "memory")

__device__ __forceinline__ void mma8(float* d, const uint32_t* a, uint32_t b0, uint32_t b1){
    asm volatile("mma.sync.aligned.m16n8k8.row.col.f32.tf32.tf32.f32 "
        "{%0,%1,%2,%3}, {%4,%5,%6,%7}, {%8,%9}, {%0,%1,%2,%3};"
        : "+f"(d[0]), "+f"(d[1]), "+f"(d[2]), "+f"(d[3])
        : "r"(a[0]), "r"(a[1]), "r"(a[2]), "r"(a[3]), "r"(b0), "r"(b1));
}

// W[k][n] row-major [128,128] -> SMEM fragment order, tf32-rounded.
__device__ void load_wfrag(const float* __restrict__ W, float* __restrict__ dst,
                           int tid, int nthr){
    for (int idx = tid; idx < 16384; idx += nthr){
        int q = idx & 3, lane = (idx >> 2) & 31, kpair = (idx >> 7) & 7, ntile = idx >> 10;
        int tig = lane & 3, g = lane >> 2;
        int kstep = kpair * 2 + (q >> 1);
        int k = kstep * 8 + tig + (q & 1) * 4;
        int n = ntile * 8 + g;
        dst[idx] = __uint_as_float(f2tf(W[k * 128 + n]));
    }
}

// A buffer: 16 rows x 128 floats, XOR-granule swizzle (granule = 4 floats):
// addr(row,k) = row*128 + (((k>>2) ^ (row&7))<<2) + (k&3)

__device__ __forceinline__ void gemm_layer(const float* __restrict__ r0,   // Ab + g*128 + tig
                                           const float* __restrict__ r1,   // Ab + (g+8)*128 + tig
                                           const float4* __restrict__ wp,  // sW + wt*1024 + lane
                                           int s,                          // g & 7
                                           float acc[4][4]){
    #pragma unroll
    for (int nt = 0; nt < 4; nt++)
        #pragma unroll
        for (int j = 0; j < 4; j++) acc[nt][j] = 0.f;
    #pragma unroll
    for (int kp = 0; kp < 8; kp++){
        int q0 = ((4*kp    ) ^ s) << 2;
        int q1 = ((4*kp + 1) ^ s) << 2;
        int q2 = ((4*kp + 2) ^ s) << 2;
        int q3 = ((4*kp + 3) ^ s) << 2;
        uint32_t af0[4] = { __float_as_uint(r0[q0]), __float_as_uint(r1[q0]),
                            __float_as_uint(r0[q1]), __float_as_uint(r1[q1]) };
        uint32_t af1[4] = { __float_as_uint(r0[q2]), __float_as_uint(r1[q2]),
                            __float_as_uint(r0[q3]), __float_as_uint(r1[q3]) };
        #pragma unroll
        for (int nt = 0; nt < 4; nt++){
            float4 w = wp[nt*256 + kp*32];
            mma8(acc[nt], af0, __float_as_uint(w.x), __float_as_uint(w.y));
            mma8(acc[nt], af1, __float_as_uint(w.z), __float_as_uint(w.w));
        }
    }
}

// staging/readback pointer for thread slice idx (row = idx>>5, granule = idx&31)
__device__ __forceinline__ float* stage_ptr(float* Ab, int idx){
    int row = idx >> 5, g4 = idx & 31;
    return Ab + row * 128 + (((g4 ^ (row & 7)) << 2));
}
// epilogue store pointer for (row, col = wt*32+nt*8+2*tig)
__device__ __forceinline__ float* epi_ptr(float* Ab, int row, int wt, int nt, int tig){
    int s = row & 7;
    int gran = (wt*8 + nt*2 + (tig >> 1)) ^ s;
    int off = (2*tig) & 2;
    return Ab + row * 128 + (gran << 2) + off;
}

// ------------------------------------------------------------------ kernel 1
__global__ void __launch_bounds__(NTHREADS, 1) pre_kernel(
    const float* __restrict__ x,
    const float* __restrict__ ew1, const float* __restrict__ eb1,
    const float* __restrict__ nw1, const float* __restrict__ nb1)
{
    extern __shared__ float sm[];
    float* sW0 = sm;
    float* sW1 = sm + 16384;
    float* sW2 = sm + 32768;
    float* sB  = sm + 49152;    // eb1 | nb1 (256)
    float* sA  = sm + 49408;    // NTEAMS * 2048

    const int tid = threadIdx.x;
    load_wfrag(ew1,         sW0, tid, NTHREADS);
    load_wfrag(ew1 + 16384, sW1, tid, NTHREADS);
    load_wfrag(nw1,         sW2, tid, NTHREADS);
    if (tid < 128){ sB[tid] = eb1[tid]; sB[128 + tid] = nb1[tid]; }
    __syncthreads();

    const int wid = tid >> 5, lane = tid & 31, team = wid >> 2, wt = wid & 3;
    const int g = lane >> 2, tig = lane & 3, tt = tid & 127, bid = 1 + team;
    float* Ab = sA + team * 2048;

    float* stp[4];
    #pragma unroll
    for (int rep = 0; rep < 4; rep++) stp[rep] = stage_ptr(Ab, tt + rep * 128);
    const float* r0 = Ab + g * 128 + tig;
    const float* r1 = Ab + (g + 8) * 128 + tig;
    const float4* wp0 = (const float4*)sW0 + wt*1024 + lane;
    const float4* wp1 = (const float4*)sW1 + wt*1024 + lane;
    const float4* wp2 = (const float4*)sW2 + wt*1024 + lane;

    for (int tile = blockIdx.x * NTEAMS + team; tile < NODE_TTILES; tile += gridDim.x * NTEAMS){
        const int n0 = tile * 16;
        const float4* s4 = (const float4*)(x + (size_t)n0 * 128);
        TBAR(bid);
        #pragma unroll
        for (int rep = 0; rep < 4; rep++){
            float4 v = s4[tt + rep * 128];
            float* p = stp[rep];
            p[0] = v.x; p[1] = v.y; p[2] = v.z; p[3] = v.w;
        }
        TBAR(bid);
        const int rA = n0 + g, rB = n0 + g + 8;

        float acc[4][4];
        #pragma unroll
        for (int L = 0; L < 3; L++){
            gemm_layer(r0, r1, (L==0)?wp0:((L==1)?wp1:wp2), g, acc);
            float* dst = (L==0) ? g_Pa : ((L==1) ? g_Pb : g_Pn);
            const float* bias = (L==0) ? sB : ((L==2) ? sB + 128 : nullptr);
            #pragma unroll
            for (int nt = 0; nt < 4; nt++){
                int col = wt*32 + nt*8 + tig*2;
                float b0 = bias ? bias[col] : 0.f, b1 = bias ? bias[col+1] : 0.f;
                float2 oA = { acc[nt][0] + b0, acc[nt][1] + b1 };
                float2 oB = { acc[nt][2] + b0, acc[nt][3] + b1 };
                *(float2*)(dst + (size_t)rA * 128 + col) = oA;
                *(float2*)(dst + (size_t)rB * 128 + col) = oB;
            }
        }
    }
}

// ------------------------------------------------------------------ kernel 2
__global__ void __launch_bounds__(NTHREADS, 1) edge_kernel(
    const int* __restrict__ ei, const float* __restrict__ ea,
    const float* __restrict__ ew1, const float* __restrict__ ew2, const float* __restrict__ ew3,
    const float* __restrict__ eb2, const float* __restrict__ eb3,
    const float* __restrict__ elg, const float* __restrict__ elb,
    float* __restrict__ outE)
{
    extern __shared__ float sm[];
    float* sW1 = sm;
    float* sW2 = sm + 16384;
    float* sW3 = sm + 32768;
    float* sB  = sm + 49152;    // eb2|eb3|gamma|beta (512)
    float* sA  = sm + 49664;    // NTEAMS * 2048

    const int tid = threadIdx.x;
    load_wfrag(ew1 + 32768, sW1, tid, NTHREADS);
    load_wfrag(ew2,         sW2, tid, NTHREADS);
    load_wfrag(ew3,         sW3, tid, NTHREADS);
    if (tid < 128){
        sB[tid] = eb2[tid]; sB[128+tid] = eb3[tid]; sB[256+tid] = elg[tid]; sB[384+tid] = elb[tid];
    }
    __syncthreads();

    const int wid = tid >> 5, lane = tid & 31, team = wid >> 2, wt = wid & 3;
    const int g = lane >> 2, tig = lane & 3, tt = tid & 127, bid = 1 + team;
    float* Ab = sA + team * 2048;

    float* stp[4];
    #pragma unroll
    for (int rep = 0; rep < 4; rep++) stp[rep] = stage_ptr(Ab, tt + rep * 128);
    const float* r0 = Ab + g * 128 + tig;
    const float* r1 = Ab + (g + 8) * 128 + tig;
    const float4* wp1 = (const float4*)sW1 + wt*1024 + lane;
    const float4* wp2 = (const float4*)sW2 + wt*1024 + lane;
    const float4* wp3 = (const float4*)sW3 + wt*1024 + lane;
    float* eg[4]; float* eh[4];
    #pragma unroll
    for (int nt = 0; nt < 4; nt++){
        eg[nt] = epi_ptr(Ab, g,     wt, nt, tig);
        eh[nt] = epi_ptr(Ab, g + 8, wt, nt, tig);
    }
    // transposed-epilogue invariants: thread owns cols c4..c4+3 of rows trowbase+{0,4,8,12}
    const int c4 = (tt & 31) * 4;
    const int trowbase = tt >> 5;
    const float4 ebv = *(const float4*)(sB + 128 + c4);
    const float4 gmv = *(const float4*)(sB + 256 + c4);
    const float4 btv = *(const float4*)(sB + 384 + c4);

    const int tstep = gridDim.x * NTEAMS;
    int tile = blockIdx.x * NTEAMS + team;

    float4 pf[4];
    int pviA = 0, pvjA = 0, pviB = 0, pvjB = 0;
    if (tile < EDGE_TTILES){
        const float4* s4 = (const float4*)(ea + (size_t)tile * 16 * 128);
        #pragma unroll
        for (int rep = 0; rep < 4; rep++) pf[rep] = s4[tt + rep * 128];
        pviA = ei[tile*16 + g];         pvjA = ei[NEDGE + tile*16 + g];
        pviB = ei[tile*16 + g + 8];     pvjB = ei[NEDGE + tile*16 + g + 8];
    }

    for (; tile < EDGE_TTILES; tile += tstep){
        const int e0 = tile * 16;
        TBAR(bid);
        #pragma unroll
        for (int rep = 0; rep < 4; rep++){
            float4 v = pf[rep];
            float* p = stp[rep];
            p[0] = v.x; p[1] = v.y; p[2] = v.z; p[3] = v.w;
        }
        TBAR(bid);

        const int viA = pviA, vjA = pvjA, viB = pviB, vjB = pvjB;

        // scatter destinations for transposed rows (used at very end; broadcast loads)
        int vjt[4];
        #pragma unroll
        for (int rep = 0; rep < 4; rep++) vjt[rep] = ei[NEDGE + e0 + trowbase + 4*rep];

        // early gathers: issue BEFORE gemm1, consume after (hidden under MMAs)
        float2 paA[4], pbA[4], paB[4], pbB[4];
        #pragma unroll
        for (int nt = 0; nt < 4; nt++){
            int col = wt*32 + nt*8 + tig*2;
            paA[nt] = __ldg((const float2*)(g_Pa + (size_t)viA*128 + col));
            pbA[nt] = __ldg((const float2*)(g_Pb + (size_t)vjA*128 + col));
            paB[nt] = __ldg((const float2*)(g_Pa + (size_t)viB*128 + col));
            pbB[nt] = __ldg((const float2*)(g_Pb + (size_t)vjB*128 + col));
        }

        float acc[4][4];
        // ---- layer 1: ea @ W1c, + Pa[i] + Pb[j], silu
        gemm_layer(r0, r1, wp1, g, acc);
        TBAR(bid);
        #pragma unroll
        for (int nt = 0; nt < 4; nt++){
            float2 wA = { __uint_as_float(f2tf(sigl(acc[nt][0] + paA[nt].x + pbA[nt].x))),
                          __uint_as_float(f2tf(sigl(acc[nt][1] + paA[nt].y + pbA[nt].y))) };
            float2 wB = { __uint_as_float(f2tf(sigl(acc[nt][2] + paB[nt].x + pbB[nt].x))),
                          __uint_as_float(f2tf(sigl(acc[nt][3] + paB[nt].y + pbB[nt].y))) };
            *(float2*)eg[nt] = wA;
            *(float2*)eh[nt] = wB;
        }
        TBAR(bid);
        // ---- layer 2: + eb2, silu
        gemm_layer(r0, r1, wp2, g, acc);
        TBAR(bid);
        #pragma unroll
        for (int nt = 0; nt < 4; nt++){
            int col = wt*32 + nt*8 + tig*2;
            float b0 = sB[col], b1 = sB[col+1];
            float2 wA = { __uint_as_float(f2tf(sigl(acc[nt][0] + b0))),
                          __uint_as_float(f2tf(sigl(acc[nt][1] + b1))) };
            float2 wB = { __uint_as_float(f2tf(sigl(acc[nt][2] + b0))),
                          __uint_as_float(f2tf(sigl(acc[nt][3] + b1))) };
            *(float2*)eg[nt] = wA;
            *(float2*)eh[nt] = wB;
        }
        TBAR(bid);

        // residual loads for transposed rows (hidden under gemm3)
        float4 rvt[4];
        #pragma unroll
        for (int rep = 0; rep < 4; rep++)
            rvt[rep] = __ldg((const float4*)(ea + (size_t)(e0 + trowbase + 4*rep)*128 + c4));

        // ---- layer 3
        gemm_layer(r0, r1, wp3, g, acc);

        // prefetch next tile (overlaps transpose + LN + writeback)
        {
            int tn = tile + tstep;
            if (tn < EDGE_TTILES){
                const float4* s4 = (const float4*)(ea + (size_t)tn * 16 * 128);
                #pragma unroll
                for (int rep = 0; rep < 4; rep++) pf[rep] = s4[tt + rep * 128];
                pviA = ei[tn*16 + g];       pvjA = ei[NEDGE + tn*16 + g];
                pviB = ei[tn*16 + g + 8];   pvjB = ei[NEDGE + tn*16 + g + 8];
            }
        }

        // transpose raw acc through Ab
        TBAR(bid);
        #pragma unroll
        for (int nt = 0; nt < 4; nt++){
            *(float2*)eg[nt] = make_float2(acc[nt][0], acc[nt][1]);
            *(float2*)eh[nt] = make_float2(acc[nt][2], acc[nt][3]);
        }
        TBAR(bid);
        // readback contiguous + bias; warp-local LN over each row
        float4 vv[4];
        float s[4], q[4];
        #pragma unroll
        for (int rep = 0; rep < 4; rep++){
            float4 v = *(const float4*)stp[rep];
            v.x += ebv.x; v.y += ebv.y; v.z += ebv.z; v.w += ebv.w;
            vv[rep] = v;
            s[rep] = v.x + v.y + v.z + v.w;
            q[rep] = v.x*v.x + v.y*v.y + v.z*v.z + v.w*v.w;
        }
        #pragma unroll
        for (int o = 1; o < 32; o <<= 1)
            #pragma unroll
            for (int rep = 0; rep < 4; rep++){
                s[rep] += __shfl_xor_sync(0xffffffffu, s[rep], o);
                q[rep] += __shfl_xor_sync(0xffffffffu, q[rep], o);
            }
        #pragma unroll
        for (int rep = 0; rep < 4; rep++){
            float mean = s[rep] * (1.f/128.f);
            float inv  = rsqrtf(q[rep] * (1.f/128.f) - mean*mean + EPS_LN);
            float4 v = vv[rep];
            float4 o;
            o.x = rvt[rep].x + (v.x - mean)*inv*gmv.x + btv.x;
            o.y = rvt[rep].y + (v.y - mean)*inv*gmv.y + btv.y;
            o.z = rvt[rep].z + (v.z - mean)*inv*gmv.z + btv.z;
            o.w = rvt[rep].w + (v.w - mean)*inv*gmv.w + btv.w;
            *(float4*)(outE + (size_t)(e0 + trowbase + 4*rep)*128 + c4) = o;
            asm volatile("red.global.add.v4.f32 [%0], {%1,%2,%3,%4};"
                         :: "l"(g_agg + (size_t)vjt[rep]*128 + c4),
                            "f"(o.x), "f"(o.y), "f"(o.z), "f"(o.w) : "memory");
        }
    }
}

// ------------------------------------------------------------------ kernel 3
__global__ void __launch_bounds__(NTHREADS, 1) node_kernel(
    const float* __restrict__ x,
    const float* __restrict__ nw1, const float* __restrict__ nw2, const float* __restrict__ nw3,
    const float* __restrict__ nb2, const float* __restrict__ nb3,
    const float* __restrict__ nlg, const float* __restrict__ nlb,
    float* __restrict__ outX)
{
    extern __shared__ float sm[];
    float* sW1 = sm;
    float* sW2 = sm + 16384;
    float* sW3 = sm + 32768;
    float* sB  = sm + 49152;
    float* sA  = sm + 49664;

    const int tid = threadIdx.x;
    load_wfrag(nw1 + 16384, sW1, tid, NTHREADS);
    load_wfrag(nw2,         sW2, tid, NTHREADS);
    load_wfrag(nw3,         sW3, tid, NTHREADS);
    if (tid < 128){
        sB[tid] = nb2[tid]; sB[128+tid] = nb3[tid]; sB[256+tid] = nlg[tid]; sB[384+tid] = nlb[tid];
    }
    __syncthreads();

    const int wid = tid >> 5, lane = tid & 31, team = wid >> 2, wt = wid & 3;
    const int g = lane >> 2, tig = lane & 3, tt = tid & 127, bid = 1 + team;
    float* Ab = sA + team * 2048;

    float* stp[4];
    #pragma unroll
    for (int rep = 0; rep < 4; rep++) stp[rep] = stage_ptr(Ab, tt + rep * 128);
    const float* r0 = Ab + g * 128 + tig;
    const float* r1 = Ab + (g + 8) * 128 + tig;
    const float4* wp1 = (const float4*)sW1 + wt*1024 + lane;
    const float4* wp2 = (const float4*)sW2 + wt*1024 + lane;
    const float4* wp3 = (const float4*)sW3 + wt*1024 + lane;
    float* eg[4]; float* eh[4];
    #pragma unroll
    for (int nt = 0; nt < 4; nt++){
        eg[nt] = epi_ptr(Ab, g,     wt, nt, tig);
        eh[nt] = epi_ptr(Ab, g + 8, wt, nt, tig);
    }
    const int c4 = (tt & 31) * 4;
    const int trowbase = tt >> 5;
    const float4 nbv = *(const float4*)(sB + 128 + c4);
    const float4 gmv = *(const float4*)(sB + 256 + c4);
    const float4 btv = *(const float4*)(sB + 384 + c4);

    for (int tile = blockIdx.x * NTEAMS + team; tile < NODE_TTILES; tile += gridDim.x * NTEAMS){
        const int n0 = tile * 16;
        const float4* s4 = (const float4*)(g_agg + (size_t)n0 * 128);
        TBAR(bid);
        #pragma unroll
        for (int rep = 0; rep < 4; rep++){
            float4 v = s4[tt + rep * 128];
            float* p = stp[rep];
            p[0] = v.x; p[1] = v.y; p[2] = v.z; p[3] = v.w;
        }
        TBAR(bid);
        const int rA = n0 + g, rB = n0 + g + 8;

        float2 pnA[4], pnB[4];
        #pragma unroll
        for (int nt = 0; nt < 4; nt++){
            int col = wt*32 + nt*8 + tig*2;
            pnA[nt] = __ldg((const float2*)(g_Pn + (size_t)rA*128 + col));
            pnB[nt] = __ldg((const float2*)(g_Pn + (size_t)rB*128 + col));
        }

        float acc[4][4];
        gemm_layer(r0, r1, wp1, g, acc);
        TBAR(bid);
        #pragma unroll
        for (int nt = 0; nt < 4; nt++){
            float2 wA = { __uint_as_float(f2tf(sigl(acc[nt][0] + pnA[nt].x))),
                          __uint_as_float(f2tf(sigl(acc[nt][1] + pnA[nt].y))) };
            float2 wB = { __uint_as_float(f2tf(sigl(acc[nt][2] + pnB[nt].x))),
                          __uint_as_float(f2tf(sigl(acc[nt][3] + pnB[nt].y))) };
            *(float2*)eg[nt] = wA;
            *(float2*)eh[nt] = wB;
        }
        TBAR(bid);
        gemm_layer(r0, r1, wp2, g, acc);
        TBAR(bid);
        #pragma unroll
        for (int nt = 0; nt < 4; nt++){
            int col = wt*32 + nt*8 + tig*2;
            float b0 = sB[col], b1 = sB[col+1];
            float2 wA = { __uint_as_float(f2tf(sigl(acc[nt][0] + b0))),
                          __uint_as_float(f2tf(sigl(acc[nt][1] + b1))) };
            float2 wB = { __uint_as_float(f2tf(sigl(acc[nt][2] + b0))),
                          __uint_as_float(f2tf(sigl(acc[nt][3] + b1))) };
            *(float2*)eg[nt] = wA;
            *(float2*)eh[nt] = wB;
        }
        TBAR(bid);

        float4 rvt[4];
        #pragma unroll
        for (int rep = 0; rep < 4; rep++)
            rvt[rep] = __ldg((const float4*)(x + (size_t)(n0 + trowbase + 4*rep)*128 + c4));

        gemm_layer(r0, r1, wp3, g, acc);

        TBAR(bid);
        #pragma unroll
        for (int nt = 0; nt < 4; nt++){
            *(float2*)eg[nt] = make_float2(acc[nt][0], acc[nt][1]);
            *(float2*)eh[nt] = make_float2(acc[nt][2], acc[nt][3]);
        }
        TBAR(bid);
        float4 vv[4];
        float s[4], q[4];
        #pragma unroll
        for (int rep = 0; rep < 4; rep++){
            float4 v = *(const float4*)stp[rep];
            v.x += nbv.x; v.y += nbv.y; v.z += nbv.z; v.w += nbv.w;
            vv[rep] = v;
            s[rep] = v.x + v.y + v.z + v.w;
            q[rep] = v.x*v.x + v.y*v.y + v.z*v.z + v.w*v.w;
        }
        #pragma unroll
        for (int o = 1; o < 32; o <<= 1)
            #pragma unroll
            for (int rep = 0; rep < 4; rep++){
                s[rep] += __shfl_xor_sync(0xffffffffu, s[rep], o);
                q[rep] += __shfl_xor_sync(0xffffffffu, q[rep], o);
            }
        #pragma unroll
        for (int rep = 0; rep < 4; rep++){
            float mean = s[rep] * (1.f/128.f);
            float inv  = rsqrtf(q[rep] * (1.f/128.f) - mean*mean + EPS_LN);
            float4 v = vv[rep];
            float4 o;
            o.x = rvt[rep].x + (v.x - mean)*inv*gmv.x + btv.x;
            o.y = rvt[rep].y + (v.y - mean)*inv*gmv.y + btv.y;
            o.z = rvt[rep].z + (v.z - mean)*inv*gmv.z + btv.z;
            o.w = rvt[rep].w + (v.w - mean)*inv*gmv.w + btv.w;
            *(float4*)(outX + (size_t)(n0 + trowbase + 4*rep)*128 + c4) = o;
        }
    }
}

// ------------------------------------------------------------------ host
extern "C" void kernel_launch(void* const* d_in, const int* in_sizes, int n_in,
                              void* d_out, int out_size) {
    const float* x   = (const float*)d_in[0];
    const int*   ei  = (const int*)  d_in[1];
    const float* ea  = (const float*)d_in[2];
    const float* ew1 = (const float*)d_in[3];
    const float* eb1 = (const float*)d_in[4];
    const float* ew2 = (const float*)d_in[5];
    const float* eb2 = (const float*)d_in[6];
    const float* ew3 = (const float*)d_in[7];
    const float* eb3 = (const float*)d_in[8];
    const float* elg = (const float*)d_in[9];
    const float* elb = (const float*)d_in[10];
    const float* nw1 = (const float*)d_in[11];
    const float* nb1 = (const float*)d_in[12];
    const float* nw2 = (const float*)d_in[13];
    const float* nb2 = (const float*)d_in[14];
    const float* nw3 = (const float*)d_in[15];
    const float* nb3 = (const float*)d_in[16];
    const float* nlg = (const float*)d_in[17];
    const float* nlb = (const float*)d_in[18];

    float* outX = (float*)d_out;
    float* outE = outX + (size_t)NNODE * 128;

    // pre:  (49152 + 256 + 4*2048) * 4 = 230400 B
    // main: (49152 + 512 + 4*2048) * 4 = 231424 B
    const size_t smem_pre  = 230400;
    const size_t smem_main = 231424;
    cudaFuncSetAttribute(pre_kernel,  cudaFuncAttributeMaxDynamicSharedMemorySize, (int)smem_pre);
    cudaFuncSetAttribute(edge_kernel, cudaFuncAttributeMaxDynamicSharedMemorySize, (int)smem_main);
    cudaFuncSetAttribute(node_kernel, cudaFuncAttributeMaxDynamicSharedMemorySize, (int)smem_main);

    void* aggp = nullptr;
    cudaGetSymbolAddress(&aggp, g_agg);
    cudaMemsetAsync(aggp, 0, sizeof(float) * (size_t)NNODE * 128, 0);

    pre_kernel<<<152, NTHREADS, smem_pre>>>(x, ew1, eb1, nw1, nb1);
    edge_kernel<<<152, NTHREADS, smem_main>>>(ei, ea, ew1, ew2, ew3, eb2, eb3, elg, elb, outE);
    node_kernel<<<152, NTHREADS, smem_main>>>(x, nw1, nw2, nw3, nb2, nb3, nlg, nlb, outX);
}

// round 12
// speedup vs baseline: 1.1178x; 1.1178x over previous
#include <cuda_runtime.h>
#include <cstdint>

#define NNODE 50000
#define NEDGE 800000
#define EPS_LN 1e-5f
#define EDGE_TTILES 50000   // 800000/16
#define NODE_TTILES 3125    // 50000/16
#define NTHREADS 512
#define NTEAMS 4

__device__ __align__(16) float g_Pa[NNODE*128];
__device__ __align__(16) float g_Pb[NNODE*128];
__device__ __align__(16) float g_Pn[NNODE*128];
__device__ __align__(16) float g_agg[NNODE*128];

__device__ __forceinline__ uint32_t f2tf(float f){
    uint32_t u; asm("cvt.rna.tf32.f32 %0, %1;" : "=r"(u) : "f"(f)); return u;
}
__device__ __forceinline__ float sigl(float v){ return v * (1.0f/(1.0f + __expf(-v))); }
__device__ __forceinline__ void st_cs2(float* p, float2 v){
    asm volatile("st.global.cs.v2.f32 [%0], {%1,%2};" :: "l"(p), "f"(v.x), "f"(v.y) : "memory");
}

#define TBAR(id) asm volatile("bar.sync %0, 128;" :: "r"(id) : "memory")

__device__ __forceinline__ void mma8(float* d, const uint32_t* a, uint32_t b0, uint32_t b1){
    asm volatile("mma.sync.aligned.m16n8k8.row.col.f32.tf32.tf32.f32 "
        "{%0,%1,%2,%3}, {%4,%5,%6,%7}, {%8,%9}, {%0,%1,%2,%3};"
        : "+f"(d[0]), "+f"(d[1]), "+f"(d[2]), "+f"(d[3])
        : "r"(a[0]), "r"(a[1]), "r"(a[2]), "r"(a[3]), "r"(b0), "r"(b1));
}

// W[k][n] row-major [128,128] -> SMEM fragment order, tf32-rounded.
__device__ void load_wfrag(const float* __restrict__ W, float* __restrict__ dst,
                           int tid, int nthr){
    for (int idx = tid; idx < 16384; idx += nthr){
        int q = idx & 3, lane = (idx >> 2) & 31, kpair = (idx >> 7) & 7, ntile = idx >> 10;
        int tig = lane & 3, g = lane >> 2;
        int kstep = kpair * 2 + (q >> 1);
        int k = kstep * 8 + tig + (q & 1) * 4;
        int n = ntile * 8 + g;
        dst[idx] = __uint_as_float(f2tf(W[k * 128 + n]));
    }
}

// A buffer: 16 rows x 128 floats, XOR-granule swizzle (granule = 4 floats):
// addr(row,k) = row*128 + (((k>>2) ^ (row&7))<<2) + (k&3)

__device__ __forceinline__ void gemm_layer(const float* __restrict__ r0,   // Ab + g*128 + tig
                                           const float* __restrict__ r1,   // Ab + (g+8)*128 + tig
                                           const float4* __restrict__ wp,  // sW + wt*1024 + lane
                                           int s,                          // g & 7
                                           float acc[4][4]){
    #pragma unroll
    for (int nt = 0; nt < 4; nt++)
        #pragma unroll
        for (int j = 0; j < 4; j++) acc[nt][j] = 0.f;
    #pragma unroll
    for (int kp = 0; kp < 8; kp++){
        int q0 = ((4*kp    ) ^ s) << 2;
        int q1 = ((4*kp + 1) ^ s) << 2;
        int q2 = ((4*kp + 2) ^ s) << 2;
        int q3 = ((4*kp + 3) ^ s) << 2;
        uint32_t af0[4] = { __float_as_uint(r0[q0]), __float_as_uint(r1[q0]),
                            __float_as_uint(r0[q1]), __float_as_uint(r1[q1]) };
        uint32_t af1[4] = { __float_as_uint(r0[q2]), __float_as_uint(r1[q2]),
                            __float_as_uint(r0[q3]), __float_as_uint(r1[q3]) };
        #pragma unroll
        for (int nt = 0; nt < 4; nt++){
            float4 w = wp[nt*256 + kp*32];
            mma8(acc[nt], af0, __float_as_uint(w.x), __float_as_uint(w.y));
            mma8(acc[nt], af1, __float_as_uint(w.z), __float_as_uint(w.w));
        }
    }
}

// staging pointer for thread slice idx (loop-invariant): float4 store target
__device__ __forceinline__ float* stage_ptr(float* Ab, int idx){
    int row = idx >> 5, g4 = idx & 31;
    return Ab + row * 128 + (((g4 ^ (row & 7)) << 2));
}
// epilogue store pointer for (row, col = wt*32+nt*8+2*tig)
__device__ __forceinline__ float* epi_ptr(float* Ab, int row, int wt, int nt, int tig){
    int s = row & 7;
    int gran = (wt*8 + nt*2 + (tig >> 1)) ^ s;
    int off = (2*tig) & 2;
    return Ab + row * 128 + (gran << 2) + off;
}

// ------------------------------------------------------------------ kernel 1
__global__ void __launch_bounds__(NTHREADS, 1) pre_kernel(
    const float* __restrict__ x,
    const float* __restrict__ ew1, const float* __restrict__ eb1,
    const float* __restrict__ nw1, const float* __restrict__ nb1)
{
    extern __shared__ float sm[];
    float* sW0 = sm;
    float* sW1 = sm + 16384;
    float* sW2 = sm + 32768;
    float* sB  = sm + 49152;    // eb1 | nb1 (256)
    float* sA  = sm + 49408;    // NTEAMS * 2048

    const int tid = threadIdx.x;
    load_wfrag(ew1,         sW0, tid, NTHREADS);
    load_wfrag(ew1 + 16384, sW1, tid, NTHREADS);
    load_wfrag(nw1,         sW2, tid, NTHREADS);
    if (tid < 128){ sB[tid] = eb1[tid]; sB[128 + tid] = nb1[tid]; }
    __syncthreads();

    const int wid = tid >> 5, lane = tid & 31, team = wid >> 2, wt = wid & 3;
    const int g = lane >> 2, tig = lane & 3, tt = tid & 127, bid = 1 + team;
    float* Ab = sA + team * 2048;

    float* stp[4];
    #pragma unroll
    for (int rep = 0; rep < 4; rep++) stp[rep] = stage_ptr(Ab, tt + rep * 128);
    const float* r0 = Ab + g * 128 + tig;
    const float* r1 = Ab + (g + 8) * 128 + tig;
    const float4* wp0 = (const float4*)sW0 + wt*1024 + lane;
    const float4* wp1 = (const float4*)sW1 + wt*1024 + lane;
    const float4* wp2 = (const float4*)sW2 + wt*1024 + lane;

    for (int tile = blockIdx.x * NTEAMS + team; tile < NODE_TTILES; tile += gridDim.x * NTEAMS){
        const int n0 = tile * 16;
        const float4* s4 = (const float4*)(x + (size_t)n0 * 128);
        TBAR(bid);
        #pragma unroll
        for (int rep = 0; rep < 4; rep++){
            float4 v = s4[tt + rep * 128];
            float* p = stp[rep];
            p[0] = v.x; p[1] = v.y; p[2] = v.z; p[3] = v.w;
        }
        TBAR(bid);
        const int rA = n0 + g, rB = n0 + g + 8;

        float acc[4][4];
        #pragma unroll
        for (int L = 0; L < 3; L++){
            gemm_layer(r0, r1, (L==0)?wp0:((L==1)?wp1:wp2), g, acc);
            float* dst = (L==0) ? g_Pa : ((L==1) ? g_Pb : g_Pn);
            const float* bias = (L==0) ? sB : ((L==2) ? sB + 128 : nullptr);
            #pragma unroll
            for (int nt = 0; nt < 4; nt++){
                int col = wt*32 + nt*8 + tig*2;
                float b0 = bias ? bias[col] : 0.f, b1 = bias ? bias[col+1] : 0.f;
                float2 oA = { acc[nt][0] + b0, acc[nt][1] + b1 };
                float2 oB = { acc[nt][2] + b0, acc[nt][3] + b1 };
                *(float2*)(dst + (size_t)rA * 128 + col) = oA;
                *(float2*)(dst + (size_t)rB * 128 + col) = oB;
            }
        }
    }
}

// ------------------------------------------------------------------ kernel 2
__global__ void __launch_bounds__(NTHREADS, 1) edge_kernel(
    const int* __restrict__ ei, const float* __restrict__ ea,
    const float* __restrict__ ew1, const float* __restrict__ ew2, const float* __restrict__ ew3,
    const float* __restrict__ eb2, const float* __restrict__ eb3,
    const float* __restrict__ elg, const float* __restrict__ elb,
    float* __restrict__ outE)
{
    extern __shared__ float sm[];
    float* sW1 = sm;
    float* sW2 = sm + 16384;
    float* sW3 = sm + 32768;
    float* sB  = sm + 49152;    // eb2|eb3|gamma|beta (512)
    float* sRed= sm + 49664;    // 256: [team][warp][rowlocal], two-phase
    float* sA  = sm + 49920;    // NTEAMS * 2048

    const int tid = threadIdx.x;
    load_wfrag(ew1 + 32768, sW1, tid, NTHREADS);
    load_wfrag(ew2,         sW2, tid, NTHREADS);
    load_wfrag(ew3,         sW3, tid, NTHREADS);
    if (tid < 128){
        sB[tid] = eb2[tid]; sB[128+tid] = eb3[tid]; sB[256+tid] = elg[tid]; sB[384+tid] = elb[tid];
    }
    __syncthreads();

    const int wid = tid >> 5, lane = tid & 31, team = wid >> 2, wt = wid & 3;
    const int g = lane >> 2, tig = lane & 3, tt = tid & 127, bid = 1 + team;
    float* Ab = sA + team * 2048;
    float* sR = sRed + team * 64;

    float* stp[4];
    #pragma unroll
    for (int rep = 0; rep < 4; rep++) stp[rep] = stage_ptr(Ab, tt + rep * 128);
    const float* r0 = Ab + g * 128 + tig;
    const float* r1 = Ab + (g + 8) * 128 + tig;
    const float4* wp1 = (const float4*)sW1 + wt*1024 + lane;
    const float4* wp2 = (const float4*)sW2 + wt*1024 + lane;
    const float4* wp3 = (const float4*)sW3 + wt*1024 + lane;
    float* eg[4]; float* eh[4];
    #pragma unroll
    for (int nt = 0; nt < 4; nt++){
        eg[nt] = epi_ptr(Ab, g,     wt, nt, tig);
        eh[nt] = epi_ptr(Ab, g + 8, wt, nt, tig);
    }

    const int tstep = gridDim.x * NTEAMS;
    int tile = blockIdx.x * NTEAMS + team;

    float4 pf[4];
    int pviA = 0, pvjA = 0, pviB = 0, pvjB = 0;
    if (tile < EDGE_TTILES){
        const float4* s4 = (const float4*)(ea + (size_t)tile * 16 * 128);
        #pragma unroll
        for (int rep = 0; rep < 4; rep++) pf[rep] = s4[tt + rep * 128];
        pviA = ei[tile*16 + g];         pvjA = ei[NEDGE + tile*16 + g];
        pviB = ei[tile*16 + g + 8];     pvjB = ei[NEDGE + tile*16 + g + 8];
    }

    for (; tile < EDGE_TTILES; tile += tstep){
        const int e0 = tile * 16;
        TBAR(bid);
        #pragma unroll
        for (int rep = 0; rep < 4; rep++){
            float4 v = pf[rep];
            float* p = stp[rep];
            p[0] = v.x; p[1] = v.y; p[2] = v.z; p[3] = v.w;
        }
        TBAR(bid);

        const int eA = e0 + g, eB = e0 + g + 8;
        const int viA = pviA, vjA = pvjA, viB = pviB, vjB = pvjB;

        // early gathers: issue BEFORE gemm1, consume after (hidden under MMAs)
        float2 paA[4], pbA[4], paB[4], pbB[4];
        #pragma unroll
        for (int nt = 0; nt < 4; nt++){
            int col = wt*32 + nt*8 + tig*2;
            paA[nt] = __ldg((const float2*)(g_Pa + (size_t)viA*128 + col));
            pbA[nt] = __ldg((const float2*)(g_Pb + (size_t)vjA*128 + col));
            paB[nt] = __ldg((const float2*)(g_Pa + (size_t)viB*128 + col));
            pbB[nt] = __ldg((const float2*)(g_Pb + (size_t)vjB*128 + col));
        }

        float acc[4][4];
        // ---- layer 1: ea @ W1c, + Pa[i] + Pb[j], silu
        gemm_layer(r0, r1, wp1, g, acc);
        TBAR(bid);
        #pragma unroll
        for (int nt = 0; nt < 4; nt++){
            float2 wA = { __uint_as_float(f2tf(sigl(acc[nt][0] + paA[nt].x + pbA[nt].x))),
                          __uint_as_float(f2tf(sigl(acc[nt][1] + paA[nt].y + pbA[nt].y))) };
            float2 wB = { __uint_as_float(f2tf(sigl(acc[nt][2] + paB[nt].x + pbB[nt].x))),
                          __uint_as_float(f2tf(sigl(acc[nt][3] + paB[nt].y + pbB[nt].y))) };
            *(float2*)eg[nt] = wA;
            *(float2*)eh[nt] = wB;
        }
        TBAR(bid);
        // ---- layer 2: + eb2, silu
        gemm_layer(r0, r1, wp2, g, acc);
        TBAR(bid);
        #pragma unroll
        for (int nt = 0; nt < 4; nt++){
            int col = wt*32 + nt*8 + tig*2;
            float b0 = sB[col], b1 = sB[col+1];
            float2 wA = { __uint_as_float(f2tf(sigl(acc[nt][0] + b0))),
                          __uint_as_float(f2tf(sigl(acc[nt][1] + b1))) };
            float2 wB = { __uint_as_float(f2tf(sigl(acc[nt][2] + b0))),
                          __uint_as_float(f2tf(sigl(acc[nt][3] + b1))) };
            *(float2*)eg[nt] = wA;
            *(float2*)eh[nt] = wB;
        }
        TBAR(bid);
        // ---- layer 3: + eb3, LN, residual, scatter
        gemm_layer(r0, r1, wp3, g, acc);

        // prefetch next tile (overlaps LN + writeback)
        {
            int tn = tile + tstep;
            if (tn < EDGE_TTILES){
                const float4* s4 = (const float4*)(ea + (size_t)tn * 16 * 128);
                #pragma unroll
                for (int rep = 0; rep < 4; rep++) pf[rep] = s4[tt + rep * 128];
                pviA = ei[tn*16 + g];       pvjA = ei[NEDGE + tn*16 + g];
                pviB = ei[tn*16 + g + 8];   pvjB = ei[NEDGE + tn*16 + g + 8];
            }
        }

        // residual loads batched here: covered by the LN shuffle sequence below
        float2 rAv[4], rBv[4];
        #pragma unroll
        for (int nt = 0; nt < 4; nt++){
            int col = wt*32 + nt*8 + tig*2;
            rAv[nt] = __ldg((const float2*)(ea + (size_t)eA*128 + col));
            rBv[nt] = __ldg((const float2*)(ea + (size_t)eB*128 + col));
        }

        float s0=0.f,q0=0.f,s1=0.f,q1=0.f;
        #pragma unroll
        for (int nt = 0; nt < 4; nt++){
            int col = wt*32 + nt*8 + tig*2;
            acc[nt][0] += sB[128+col]; acc[nt][1] += sB[128+col+1];
            acc[nt][2] += sB[128+col]; acc[nt][3] += sB[128+col+1];
            s0 += acc[nt][0]+acc[nt][1]; q0 += acc[nt][0]*acc[nt][0]+acc[nt][1]*acc[nt][1];
            s1 += acc[nt][2]+acc[nt][3]; q1 += acc[nt][2]*acc[nt][2]+acc[nt][3]*acc[nt][3];
        }
        #pragma unroll
        for (int o = 1; o < 4; o <<= 1){
            s0 += __shfl_xor_sync(0xffffffffu, s0, o);
            q0 += __shfl_xor_sync(0xffffffffu, q0, o);
            s1 += __shfl_xor_sync(0xffffffffu, s1, o);
            q1 += __shfl_xor_sync(0xffffffffu, q1, o);
        }
        // two-phase cross-warp LN reduce (3 barriers)
        if (tig == 0){
            sR[wt*16 + g] = s0;
            sR[wt*16 + g + 8] = s1;
        }
        TBAR(bid);
        float mA, mB;
        {
            float tA = 0.f, tB = 0.f;
            #pragma unroll
            for (int w2 = 0; w2 < 4; w2++){ tA += sR[w2*16 + g]; tB += sR[w2*16 + g + 8]; }
            mA = tA * (1.f/128.f); mB = tB * (1.f/128.f);
        }
        TBAR(bid);
        if (tig == 0){
            sR[wt*16 + g] = q0;
            sR[wt*16 + g + 8] = q1;
        }
        TBAR(bid);
        float iA, iB;
        {
            float tA = 0.f, tB = 0.f;
            #pragma unroll
            for (int w2 = 0; w2 < 4; w2++){ tA += sR[w2*16 + g]; tB += sR[w2*16 + g + 8]; }
            iA = rsqrtf(tA * (1.f/128.f) - mA*mA + EPS_LN);
            iB = rsqrtf(tB * (1.f/128.f) - mB*mB + EPS_LN);
        }
        #pragma unroll
        for (int nt = 0; nt < 4; nt++){
            int col = wt*32 + nt*8 + tig*2;
            float gm0 = sB[256+col], gm1 = sB[256+col+1];
            float bt0 = sB[384+col], bt1 = sB[384+col+1];
            float2 oA = { rAv[nt].x + (acc[nt][0]-mA)*iA*gm0 + bt0,
                          rAv[nt].y + (acc[nt][1]-mA)*iA*gm1 + bt1 };
            float2 oB = { rBv[nt].x + (acc[nt][2]-mB)*iB*gm0 + bt0,
                          rBv[nt].y + (acc[nt][3]-mB)*iB*gm1 + bt1 };
            st_cs2(outE + (size_t)eA*128 + col, oA);
            st_cs2(outE + (size_t)eB*128 + col, oB);
            asm volatile("red.global.add.v2.f32 [%0], {%1,%2};"
                         :: "l"(g_agg + (size_t)vjA*128 + col), "f"(oA.x), "f"(oA.y) : "memory");
            asm volatile("red.global.add.v2.f32 [%0], {%1,%2};"
                         :: "l"(g_agg + (size_t)vjB*128 + col), "f"(oB.x), "f"(oB.y) : "memory");
        }
    }
}

// ------------------------------------------------------------------ kernel 3
__global__ void __launch_bounds__(NTHREADS, 1) node_kernel(
    const float* __restrict__ x,
    const float* __restrict__ nw1, const float* __restrict__ nw2, const float* __restrict__ nw3,
    const float* __restrict__ nb2, const float* __restrict__ nb3,
    const float* __restrict__ nlg, const float* __restrict__ nlb,
    float* __restrict__ outX)
{
    extern __shared__ float sm[];
    float* sW1 = sm;
    float* sW2 = sm + 16384;
    float* sW3 = sm + 32768;
    float* sB  = sm + 49152;
    float* sRed= sm + 49664;
    float* sA  = sm + 49920;

    const int tid = threadIdx.x;
    load_wfrag(nw1 + 16384, sW1, tid, NTHREADS);
    load_wfrag(nw2,         sW2, tid, NTHREADS);
    load_wfrag(nw3,         sW3, tid, NTHREADS);
    if (tid < 128){
        sB[tid] = nb2[tid]; sB[128+tid] = nb3[tid]; sB[256+tid] = nlg[tid]; sB[384+tid] = nlb[tid];
    }
    __syncthreads();

    const int wid = tid >> 5, lane = tid & 31, team = wid >> 2, wt = wid & 3;
    const int g = lane >> 2, tig = lane & 3, tt = tid & 127, bid = 1 + team;
    float* Ab = sA + team * 2048;
    float* sR = sRed + team * 64;

    float* stp[4];
    #pragma unroll
    for (int rep = 0; rep < 4; rep++) stp[rep] = stage_ptr(Ab, tt + rep * 128);
    const float* r0 = Ab + g * 128 + tig;
    const float* r1 = Ab + (g + 8) * 128 + tig;
    const float4* wp1 = (const float4*)sW1 + wt*1024 + lane;
    const float4* wp2 = (const float4*)sW2 + wt*1024 + lane;
    const float4* wp3 = (const float4*)sW3 + wt*1024 + lane;
    float* eg[4]; float* eh[4];
    #pragma unroll
    for (int nt = 0; nt < 4; nt++){
        eg[nt] = epi_ptr(Ab, g,     wt, nt, tig);
        eh[nt] = epi_ptr(Ab, g + 8, wt, nt, tig);
    }

    for (int tile = blockIdx.x * NTEAMS + team; tile < NODE_TTILES; tile += gridDim.x * NTEAMS){
        const int n0 = tile * 16;
        const float4* s4 = (const float4*)(g_agg + (size_t)n0 * 128);
        TBAR(bid);
        #pragma unroll
        for (int rep = 0; rep < 4; rep++){
            float4 v = s4[tt + rep * 128];
            float* p = stp[rep];
            p[0] = v.x; p[1] = v.y; p[2] = v.z; p[3] = v.w;
        }
        TBAR(bid);
        const int rA = n0 + g, rB = n0 + g + 8;

        float2 pnA[4], pnB[4];
        #pragma unroll
        for (int nt = 0; nt < 4; nt++){
            int col = wt*32 + nt*8 + tig*2;
            pnA[nt] = __ldg((const float2*)(g_Pn + (size_t)rA*128 + col));
            pnB[nt] = __ldg((const float2*)(g_Pn + (size_t)rB*128 + col));
        }

        float acc[4][4];
        gemm_layer(r0, r1, wp1, g, acc);
        TBAR(bid);
        #pragma unroll
        for (int nt = 0; nt < 4; nt++){
            float2 wA = { __uint_as_float(f2tf(sigl(acc[nt][0] + pnA[nt].x))),
                          __uint_as_float(f2tf(sigl(acc[nt][1] + pnA[nt].y))) };
            float2 wB = { __uint_as_float(f2tf(sigl(acc[nt][2] + pnB[nt].x))),
                          __uint_as_float(f2tf(sigl(acc[nt][3] + pnB[nt].y))) };
            *(float2*)eg[nt] = wA;
            *(float2*)eh[nt] = wB;
        }
        TBAR(bid);
        gemm_layer(r0, r1, wp2, g, acc);
        TBAR(bid);
        #pragma unroll
        for (int nt = 0; nt < 4; nt++){
            int col = wt*32 + nt*8 + tig*2;
            float b0 = sB[col], b1 = sB[col+1];
            float2 wA = { __uint_as_float(f2tf(sigl(acc[nt][0] + b0))),
                          __uint_as_float(f2tf(sigl(acc[nt][1] + b1))) };
            float2 wB = { __uint_as_float(f2tf(sigl(acc[nt][2] + b0))),
                          __uint_as_float(f2tf(sigl(acc[nt][3] + b1))) };
            *(float2*)eg[nt] = wA;
            *(float2*)eh[nt] = wB;
        }
        TBAR(bid);
        gemm_layer(r0, r1, wp3, g, acc);

        // residual loads batched before LN shuffles
        float2 rxA[4], rxB[4];
        #pragma unroll
        for (int nt = 0; nt < 4; nt++){
            int col = wt*32 + nt*8 + tig*2;
            rxA[nt] = __ldg((const float2*)(x + (size_t)rA*128 + col));
            rxB[nt] = __ldg((const float2*)(x + (size_t)rB*128 + col));
        }

        float s0=0.f,q0=0.f,s1=0.f,q1=0.f;
        #pragma unroll
        for (int nt = 0; nt < 4; nt++){
            int col = wt*32 + nt*8 + tig*2;
            acc[nt][0] += sB[128+col]; acc[nt][1] += sB[128+col+1];
            acc[nt][2] += sB[128+col]; acc[nt][3] += sB[128+col+1];
            s0 += acc[nt][0]+acc[nt][1]; q0 += acc[nt][0]*acc[nt][0]+acc[nt][1]*acc[nt][1];
            s1 += acc[nt][2]+acc[nt][3]; q1 += acc[nt][2]*acc[nt][2]+acc[nt][3]*acc[nt][3];
        }
        #pragma unroll
        for (int o = 1; o < 4; o <<= 1){
            s0 += __shfl_xor_sync(0xffffffffu, s0, o);
            q0 += __shfl_xor_sync(0xffffffffu, q0, o);
            s1 += __shfl_xor_sync(0xffffffffu, s1, o);
            q1 += __shfl_xor_sync(0xffffffffu, q1, o);
        }
        if (tig == 0){
            sR[wt*16 + g] = s0;
            sR[wt*16 + g + 8] = s1;
        }
        TBAR(bid);
        float mA, mB;
        {
            float tA = 0.f, tB = 0.f;
            #pragma unroll
            for (int w2 = 0; w2 < 4; w2++){ tA += sR[w2*16 + g]; tB += sR[w2*16 + g + 8]; }
            mA = tA * (1.f/128.f); mB = tB * (1.f/128.f);
        }
        TBAR(bid);
        if (tig == 0){
            sR[wt*16 + g] = q0;
            sR[wt*16 + g + 8] = q1;
        }
        TBAR(bid);
        float iA, iB;
        {
            float tA = 0.f, tB = 0.f;
            #pragma unroll
            for (int w2 = 0; w2 < 4; w2++){ tA += sR[w2*16 + g]; tB += sR[w2*16 + g + 8]; }
            iA = rsqrtf(tA * (1.f/128.f) - mA*mA + EPS_LN);
            iB = rsqrtf(tB * (1.f/128.f) - mB*mB + EPS_LN);
        }
        #pragma unroll
        for (int nt = 0; nt < 4; nt++){
            int col = wt*32 + nt*8 + tig*2;
            float gm0 = sB[256+col], gm1 = sB[256+col+1];
            float bt0 = sB[384+col], bt1 = sB[384+col+1];
            float2 oA = { rxA[nt].x + (acc[nt][0]-mA)*iA*gm0 + bt0,
                          rxA[nt].y + (acc[nt][1]-mA)*iA*gm1 + bt1 };
            float2 oB = { rxB[nt].x + (acc[nt][2]-mB)*iB*gm0 + bt0,
                          rxB[nt].y + (acc[nt][3]-mB)*iB*gm1 + bt1 };
            st_cs2(outX + (size_t)rA*128 + col, oA);
            st_cs2(outX + (size_t)rB*128 + col, oB);
        }
    }
}

// ------------------------------------------------------------------ host
extern "C" void kernel_launch(void* const* d_in, const int* in_sizes, int n_in,
                              void* d_out, int out_size) {
    const float* x   = (const float*)d_in[0];
    const int*   ei  = (const int*)  d_in[1];
    const float* ea  = (const float*)d_in[2];
    const float* ew1 = (const float*)d_in[3];
    const float* eb1 = (const float*)d_in[4];
    const float* ew2 = (const float*)d_in[5];
    const float* eb2 = (const float*)d_in[6];
    const float* ew3 = (const float*)d_in[7];
    const float* eb3 = (const float*)d_in[8];
    const float* elg = (const float*)d_in[9];
    const float* elb = (const float*)d_in[10];
    const float* nw1 = (const float*)d_in[11];
    const float* nb1 = (const float*)d_in[12];
    const float* nw2 = (const float*)d_in[13];
    const float* nb2 = (const float*)d_in[14];
    const float* nw3 = (const float*)d_in[15];
    const float* nb3 = (const float*)d_in[16];
    const float* nlg = (const float*)d_in[17];
    const float* nlb = (const float*)d_in[18];

    float* outX = (float*)d_out;
    float* outE = outX + (size_t)NNODE * 128;

    // pre:  (49152 + 256 + 4*2048) * 4        = 230400 B
    // main: (49152 + 512 + 256 + 4*2048) * 4  = 232448 B
    const size_t smem_pre  = 230400;
    const size_t smem_main = 232448;
    cudaFuncSetAttribute(pre_kernel,  cudaFuncAttributeMaxDynamicSharedMemorySize, (int)smem_pre);
    cudaFuncSetAttribute(edge_kernel, cudaFuncAttributeMaxDynamicSharedMemorySize, (int)smem_main);
    cudaFuncSetAttribute(node_kernel, cudaFuncAttributeMaxDynamicSharedMemorySize, (int)smem_main);

    void* aggp = nullptr;
    cudaGetSymbolAddress(&aggp, g_agg);
    cudaMemsetAsync(aggp, 0, sizeof(float) * (size_t)NNODE * 128, 0);

    pre_kernel<<<152, NTHREADS, smem_pre>>>(x, ew1, eb1, nw1, nb1);
    edge_kernel<<<152, NTHREADS, smem_main>>>(ei, ea, ew1, ew2, ew3, eb2, eb3, elg, elb, outE);
    node_kernel<<<152, NTHREADS, smem_main>>>(x, nw1, nw2, nw3, nb2, nb3, nlg, nlb, outX);
}